// round 1
// baseline (speedup 1.0000x reference)
#include <cuda_runtime.h>

#define N_NODES 100000
#define IN_F    256
#define HID_F   128
#define OUT_F   32

// Scratch: __device__ globals (no allocation allowed anywhere).
__device__ float g_h0[(size_t)N_NODES * HID_F];  // x @ W1
__device__ float g_h1[(size_t)N_NODES * HID_F];  // spmm1 out
__device__ float g_h2[(size_t)N_NODES * OUT_F];  // relu(h1) @ W2

// ---------------------------------------------------------------------------
// Zero kernels (d_out is poisoned to 0xAA; h1 accumulates atomics)
// ---------------------------------------------------------------------------
__global__ void zero_h1_kernel() {
    size_t i = (size_t)blockIdx.x * blockDim.x + threadIdx.x;
    size_t n4 = (size_t)N_NODES * HID_F / 4;
    if (i < n4) ((float4*)g_h1)[i] = make_float4(0.f, 0.f, 0.f, 0.f);
}

__global__ void zero_out_kernel(float* out) {
    size_t i = (size_t)blockIdx.x * blockDim.x + threadIdx.x;
    size_t n4 = (size_t)N_NODES * OUT_F / 4;
    if (i < n4) ((float4*)out)[i] = make_float4(0.f, 0.f, 0.f, 0.f);
}

// ---------------------------------------------------------------------------
// GEMM1: h0[M,128] = x[M,256] @ W1[256,128]
// Tiled fp32: BM=64, BN=128, BK=32; 256 threads; each thread 8x4 outputs.
// ---------------------------------------------------------------------------
__global__ __launch_bounds__(256) void gemm1_kernel(const float* __restrict__ X,
                                                    const float* __restrict__ W1) {
    __shared__ float As[64][32];
    __shared__ float Bs[32][128];

    const int tid = threadIdx.x;
    const int tx = tid & 31;        // col group: cols tx*4 .. tx*4+3
    const int ty = tid >> 5;        // row group: rows ty*8 .. ty*8+7
    const int m0 = blockIdx.x * 64;

    float c[8][4];
#pragma unroll
    for (int i = 0; i < 8; i++)
#pragma unroll
        for (int j = 0; j < 4; j++) c[i][j] = 0.f;

    for (int k0 = 0; k0 < IN_F; k0 += 32) {
        // Load A tile: 64x32 floats = 512 float4, 2 per thread
#pragma unroll
        for (int i = tid; i < 512; i += 256) {
            int r  = i >> 3;
            int cc = (i & 7) * 4;
            int gm = m0 + r;
            float4 v = make_float4(0.f, 0.f, 0.f, 0.f);
            if (gm < N_NODES)
                v = *(const float4*)(X + (size_t)gm * IN_F + k0 + cc);
            *(float4*)&As[r][cc] = v;
        }
        // Load B tile: 32x128 floats = 1024 float4, 4 per thread
#pragma unroll
        for (int i = tid; i < 1024; i += 256) {
            int r  = i >> 5;
            int cc = (i & 31) * 4;
            *(float4*)&Bs[r][cc] = *(const float4*)(W1 + (size_t)(k0 + r) * HID_F + cc);
        }
        __syncthreads();

#pragma unroll
        for (int kk = 0; kk < 32; kk++) {
            float4 b = *(const float4*)&Bs[kk][tx * 4];
            float a[8];
#pragma unroll
            for (int i = 0; i < 8; i++) a[i] = As[ty * 8 + i][kk];
#pragma unroll
            for (int i = 0; i < 8; i++) {
                c[i][0] = fmaf(a[i], b.x, c[i][0]);
                c[i][1] = fmaf(a[i], b.y, c[i][1]);
                c[i][2] = fmaf(a[i], b.z, c[i][2]);
                c[i][3] = fmaf(a[i], b.w, c[i][3]);
            }
        }
        __syncthreads();
    }

#pragma unroll
    for (int i = 0; i < 8; i++) {
        int gm = m0 + ty * 8 + i;
        if (gm < N_NODES) {
            float4 v = make_float4(c[i][0], c[i][1], c[i][2], c[i][3]);
            *(float4*)(g_h0 + (size_t)gm * HID_F + tx * 4) = v;
        }
    }
}

// ---------------------------------------------------------------------------
// SpMM1 (F=128): g_h1[rows[e]] += vals[e] * g_h0[cols[e]]
// One warp per edge; each lane handles a float4 (4 scalar atomicAdds).
// ---------------------------------------------------------------------------
__global__ __launch_bounds__(256) void spmm128_kernel(const int* __restrict__ rows,
                                                      const int* __restrict__ cols,
                                                      const float* __restrict__ vals,
                                                      int nE) {
    int gt = blockIdx.x * blockDim.x + threadIdx.x;
    int e = gt >> 5;
    if (e >= nE) return;
    int lane = gt & 31;

    int r = rows[e];
    int c = cols[e];
    float v = vals[e];

    float4 m = *(const float4*)(g_h0 + (size_t)c * HID_F + lane * 4);
    float* yp = g_h1 + (size_t)r * HID_F + lane * 4;
    atomicAdd(yp + 0, m.x * v);
    atomicAdd(yp + 1, m.y * v);
    atomicAdd(yp + 2, m.z * v);
    atomicAdd(yp + 3, m.w * v);
}

// ---------------------------------------------------------------------------
// GEMM2: g_h2[M,32] = relu(g_h1)[M,128] @ W2[128,32]
// W2 fully in smem (16KB); one thread per node row.
// ---------------------------------------------------------------------------
__global__ __launch_bounds__(256) void gemm2_kernel(const float* __restrict__ W2) {
    __shared__ float Ws[HID_F * OUT_F];  // 4096 floats
    for (int i = threadIdx.x; i < HID_F * OUT_F; i += 256) Ws[i] = W2[i];
    __syncthreads();

    int r = blockIdx.x * 256 + threadIdx.x;
    if (r >= N_NODES) return;

    float acc[OUT_F];
#pragma unroll
    for (int n = 0; n < OUT_F; n++) acc[n] = 0.f;

    const float4* hp = (const float4*)(g_h1 + (size_t)r * HID_F);
#pragma unroll 4
    for (int k4 = 0; k4 < HID_F / 4; k4++) {
        float4 h = hp[k4];
        h.x = fmaxf(h.x, 0.f);
        h.y = fmaxf(h.y, 0.f);
        h.z = fmaxf(h.z, 0.f);
        h.w = fmaxf(h.w, 0.f);
        int k = k4 * 4;
        float hh[4] = {h.x, h.y, h.z, h.w};
#pragma unroll
        for (int dk = 0; dk < 4; dk++) {
#pragma unroll
            for (int n = 0; n < OUT_F; n += 4) {
                float4 w = *(const float4*)&Ws[(k + dk) * OUT_F + n];
                acc[n + 0] = fmaf(hh[dk], w.x, acc[n + 0]);
                acc[n + 1] = fmaf(hh[dk], w.y, acc[n + 1]);
                acc[n + 2] = fmaf(hh[dk], w.z, acc[n + 2]);
                acc[n + 3] = fmaf(hh[dk], w.w, acc[n + 3]);
            }
        }
    }

    float* op = g_h2 + (size_t)r * OUT_F;
#pragma unroll
    for (int n = 0; n < OUT_F; n += 4)
        *(float4*)(op + n) = make_float4(acc[n], acc[n + 1], acc[n + 2], acc[n + 3]);
}

// ---------------------------------------------------------------------------
// SpMM2 (F=32): out[rows[e]] += vals[e] * g_h2[cols[e]]
// One warp per edge; one float per lane.
// ---------------------------------------------------------------------------
__global__ __launch_bounds__(256) void spmm32_kernel(const int* __restrict__ rows,
                                                     const int* __restrict__ cols,
                                                     const float* __restrict__ vals,
                                                     float* __restrict__ out,
                                                     int nE) {
    int gt = blockIdx.x * blockDim.x + threadIdx.x;
    int e = gt >> 5;
    if (e >= nE) return;
    int lane = gt & 31;

    int r = rows[e];
    int c = cols[e];
    float v = vals[e];

    float m = g_h2[(size_t)c * OUT_F + lane] * v;
    atomicAdd(out + (size_t)r * OUT_F + lane, m);
}

// ---------------------------------------------------------------------------
// Launch
// Inputs (metadata order): x, adj_rows, adj_cols, adj_vals, W1, W2
// ---------------------------------------------------------------------------
extern "C" void kernel_launch(void* const* d_in, const int* in_sizes, int n_in,
                              void* d_out, int out_size) {
    const float* x    = (const float*)d_in[0];
    const int*   rows = (const int*)d_in[1];
    const int*   cols = (const int*)d_in[2];
    const float* vals = (const float*)d_in[3];
    const float* W1   = (const float*)d_in[4];
    const float* W2   = (const float*)d_in[5];
    float* out = (float*)d_out;

    const int nE = in_sizes[1];

    // Zero h1 and out
    {
        size_t n4 = (size_t)N_NODES * HID_F / 4;
        zero_h1_kernel<<<(unsigned)((n4 + 255) / 256), 256>>>();
        size_t o4 = (size_t)N_NODES * OUT_F / 4;
        zero_out_kernel<<<(unsigned)((o4 + 255) / 256), 256>>>(out);
    }

    // GEMM1: x @ W1 -> h0
    gemm1_kernel<<<(N_NODES + 63) / 64, 256>>>(x, W1);

    // SpMM1: h1 = A_hat @ h0
    {
        long long threads = (long long)nE * 32;
        int blocks = (int)((threads + 255) / 256);
        spmm128_kernel<<<blocks, 256>>>(rows, cols, vals, nE);
    }

    // GEMM2: h2 = relu(h1) @ W2
    gemm2_kernel<<<(N_NODES + 255) / 256, 256>>>(W2);

    // SpMM2: out = A_hat @ h2
    {
        long long threads = (long long)nE * 32;
        int blocks = (int)((threads + 255) / 256);
        spmm32_kernel<<<blocks, 256>>>(rows, cols, vals, out, nE);
    }
}

// round 2
// speedup vs baseline: 1.6830x; 1.6830x over previous
#include <cuda_runtime.h>

#define N_NODES 100000
#define IN_F    256
#define HID_F   128
#define OUT_F   32

// Scratch: __device__ globals (no allocation allowed anywhere).
__device__ float g_h0[(size_t)N_NODES * HID_F];  // x @ W1
__device__ float g_h1[(size_t)N_NODES * HID_F];  // spmm1 out
__device__ float g_h2[(size_t)N_NODES * OUT_F];  // relu(h1) @ W2

// ---------------------------------------------------------------------------
// Zero kernels (d_out is poisoned to 0xAA; h1 accumulates atomics)
// ---------------------------------------------------------------------------
__global__ void zero_h1_kernel() {
    size_t i = (size_t)blockIdx.x * blockDim.x + threadIdx.x;
    size_t n4 = (size_t)N_NODES * HID_F / 4;
    if (i < n4) ((float4*)g_h1)[i] = make_float4(0.f, 0.f, 0.f, 0.f);
}

__global__ void zero_out_kernel(float* out) {
    size_t i = (size_t)blockIdx.x * blockDim.x + threadIdx.x;
    size_t n4 = (size_t)N_NODES * OUT_F / 4;
    if (i < n4) ((float4*)out)[i] = make_float4(0.f, 0.f, 0.f, 0.f);
}

// ---------------------------------------------------------------------------
// GEMM1: h0[M,128] = x[M,256] @ W1[256,128]
// 128x128 tile, BK=16, 256 threads, 8x8 per-thread microtile.
// ---------------------------------------------------------------------------
__global__ __launch_bounds__(256) void gemm1_kernel(const float* __restrict__ X,
                                                    const float* __restrict__ W1) {
    __shared__ float As[16][128];   // transposed: As[k][m]
    __shared__ float Bs[16][128];   // Bs[k][n]

    const int tid = threadIdx.x;
    const int tx = tid & 15;        // col group: cols tx*8 .. tx*8+7
    const int ty = tid >> 4;        // row group: rows ty*8 .. ty*8+7
    const int m0 = blockIdx.x * 128;

    float acc[8][8];
#pragma unroll
    for (int i = 0; i < 8; i++)
#pragma unroll
        for (int j = 0; j < 8; j++) acc[i][j] = 0.f;

    for (int k0 = 0; k0 < IN_F; k0 += 16) {
        // A tile: 128 rows x 16 cols = 512 float4 (2 per thread), store transposed
#pragma unroll
        for (int i = tid; i < 512; i += 256) {
            int r  = i >> 2;          // 0..127
            int c4 = (i & 3) * 4;     // 0,4,8,12
            int gm = m0 + r;
            float4 v = make_float4(0.f, 0.f, 0.f, 0.f);
            if (gm < N_NODES)
                v = *(const float4*)(X + (size_t)gm * IN_F + k0 + c4);
            As[c4 + 0][r] = v.x;
            As[c4 + 1][r] = v.y;
            As[c4 + 2][r] = v.z;
            As[c4 + 3][r] = v.w;
        }
        // B tile: 16 rows x 128 cols = 512 float4 (2 per thread)
#pragma unroll
        for (int i = tid; i < 512; i += 256) {
            int r  = i >> 5;          // 0..15
            int c4 = (i & 31) * 4;    // 0..124
            *(float4*)&Bs[r][c4] = *(const float4*)(W1 + (size_t)(k0 + r) * HID_F + c4);
        }
        __syncthreads();

#pragma unroll
        for (int kk = 0; kk < 16; kk++) {
            float a[8], b[8];
            float4 a0 = *(const float4*)&As[kk][ty * 8];
            float4 a1 = *(const float4*)&As[kk][ty * 8 + 4];
            float4 b0 = *(const float4*)&Bs[kk][tx * 8];
            float4 b1 = *(const float4*)&Bs[kk][tx * 8 + 4];
            a[0] = a0.x; a[1] = a0.y; a[2] = a0.z; a[3] = a0.w;
            a[4] = a1.x; a[5] = a1.y; a[6] = a1.z; a[7] = a1.w;
            b[0] = b0.x; b[1] = b0.y; b[2] = b0.z; b[3] = b0.w;
            b[4] = b1.x; b[5] = b1.y; b[6] = b1.z; b[7] = b1.w;
#pragma unroll
            for (int i = 0; i < 8; i++)
#pragma unroll
                for (int j = 0; j < 8; j++)
                    acc[i][j] = fmaf(a[i], b[j], acc[i][j]);
        }
        __syncthreads();
    }

#pragma unroll
    for (int i = 0; i < 8; i++) {
        int gm = m0 + ty * 8 + i;
        if (gm < N_NODES) {
            float* op = g_h0 + (size_t)gm * HID_F + tx * 8;
            *(float4*)(op + 0) = make_float4(acc[i][0], acc[i][1], acc[i][2], acc[i][3]);
            *(float4*)(op + 4) = make_float4(acc[i][4], acc[i][5], acc[i][6], acc[i][7]);
        }
    }
}

// ---------------------------------------------------------------------------
// SpMM1 (F=128): g_h1[rows[e]] += vals[e] * g_h0[cols[e]]
// One warp per edge; each lane handles a float4 via ONE red.global.add.v4.f32.
// ---------------------------------------------------------------------------
__global__ __launch_bounds__(256) void spmm128_kernel(const int* __restrict__ rows,
                                                      const int* __restrict__ cols,
                                                      const float* __restrict__ vals,
                                                      int nE) {
    int gt = blockIdx.x * blockDim.x + threadIdx.x;
    int e = gt >> 5;
    if (e >= nE) return;
    int lane = gt & 31;

    int r = __ldg(rows + e);
    int c = __ldg(cols + e);
    float v = __ldg(vals + e);

    float4 m = *(const float4*)(g_h0 + (size_t)c * HID_F + lane * 4);
    float* yp = g_h1 + (size_t)r * HID_F + lane * 4;
    asm volatile("red.global.add.v4.f32 [%0], {%1,%2,%3,%4};"
                 :: "l"(yp), "f"(m.x * v), "f"(m.y * v), "f"(m.z * v), "f"(m.w * v)
                 : "memory");
}

// ---------------------------------------------------------------------------
// GEMM2: g_h2[M,32] = relu(g_h1)[M,128] @ W2[128,32]
// W2 fully in smem (16KB); one thread per node row.
// ---------------------------------------------------------------------------
__global__ __launch_bounds__(256) void gemm2_kernel(const float* __restrict__ W2) {
    __shared__ float Ws[HID_F * OUT_F];  // 4096 floats
    for (int i = threadIdx.x; i < HID_F * OUT_F; i += 256) Ws[i] = W2[i];
    __syncthreads();

    int r = blockIdx.x * 256 + threadIdx.x;
    if (r >= N_NODES) return;

    float acc[OUT_F];
#pragma unroll
    for (int n = 0; n < OUT_F; n++) acc[n] = 0.f;

    const float4* hp = (const float4*)(g_h1 + (size_t)r * HID_F);
#pragma unroll 4
    for (int k4 = 0; k4 < HID_F / 4; k4++) {
        float4 h = hp[k4];
        h.x = fmaxf(h.x, 0.f);
        h.y = fmaxf(h.y, 0.f);
        h.z = fmaxf(h.z, 0.f);
        h.w = fmaxf(h.w, 0.f);
        int k = k4 * 4;
        float hh[4] = {h.x, h.y, h.z, h.w};
#pragma unroll
        for (int dk = 0; dk < 4; dk++) {
#pragma unroll
            for (int n = 0; n < OUT_F; n += 4) {
                float4 w = *(const float4*)&Ws[(k + dk) * OUT_F + n];
                acc[n + 0] = fmaf(hh[dk], w.x, acc[n + 0]);
                acc[n + 1] = fmaf(hh[dk], w.y, acc[n + 1]);
                acc[n + 2] = fmaf(hh[dk], w.z, acc[n + 2]);
                acc[n + 3] = fmaf(hh[dk], w.w, acc[n + 3]);
            }
        }
    }

    float* op = g_h2 + (size_t)r * OUT_F;
#pragma unroll
    for (int n = 0; n < OUT_F; n += 4)
        *(float4*)(op + n) = make_float4(acc[n], acc[n + 1], acc[n + 2], acc[n + 3]);
}

// ---------------------------------------------------------------------------
// SpMM2 (F=32): out[rows[e]] += vals[e] * g_h2[cols[e]]
// 8 lanes per edge; each lane does one red.global.add.v4.f32.
// ---------------------------------------------------------------------------
__global__ __launch_bounds__(256) void spmm32_kernel(const int* __restrict__ rows,
                                                     const int* __restrict__ cols,
                                                     const float* __restrict__ vals,
                                                     float* __restrict__ out,
                                                     int nE) {
    int gt = blockIdx.x * blockDim.x + threadIdx.x;
    int e = gt >> 3;
    if (e >= nE) return;
    int lane = gt & 7;

    int r = __ldg(rows + e);
    int c = __ldg(cols + e);
    float v = __ldg(vals + e);

    float4 m = *(const float4*)(g_h2 + (size_t)c * OUT_F + lane * 4);
    float* yp = out + (size_t)r * OUT_F + lane * 4;
    asm volatile("red.global.add.v4.f32 [%0], {%1,%2,%3,%4};"
                 :: "l"(yp), "f"(m.x * v), "f"(m.y * v), "f"(m.z * v), "f"(m.w * v)
                 : "memory");
}

// ---------------------------------------------------------------------------
// Launch
// Inputs (metadata order): x, adj_rows, adj_cols, adj_vals, W1, W2
// ---------------------------------------------------------------------------
extern "C" void kernel_launch(void* const* d_in, const int* in_sizes, int n_in,
                              void* d_out, int out_size) {
    const float* x    = (const float*)d_in[0];
    const int*   rows = (const int*)d_in[1];
    const int*   cols = (const int*)d_in[2];
    const float* vals = (const float*)d_in[3];
    const float* W1   = (const float*)d_in[4];
    const float* W2   = (const float*)d_in[5];
    float* out = (float*)d_out;

    const int nE = in_sizes[1];

    // Zero h1 and out
    {
        size_t n4 = (size_t)N_NODES * HID_F / 4;
        zero_h1_kernel<<<(unsigned)((n4 + 255) / 256), 256>>>();
        size_t o4 = (size_t)N_NODES * OUT_F / 4;
        zero_out_kernel<<<(unsigned)((o4 + 255) / 256), 256>>>(out);
    }

    // GEMM1: x @ W1 -> h0
    gemm1_kernel<<<(N_NODES + 127) / 128, 256>>>(x, W1);

    // SpMM1: h1 = A_hat @ h0
    {
        long long threads = (long long)nE * 32;
        int blocks = (int)((threads + 255) / 256);
        spmm128_kernel<<<blocks, 256>>>(rows, cols, vals, nE);
    }

    // GEMM2: h2 = relu(h1) @ W2
    gemm2_kernel<<<(N_NODES + 255) / 256, 256>>>(W2);

    // SpMM2: out = A_hat @ h2
    {
        long long threads = (long long)nE * 8;
        int blocks = (int)((threads + 255) / 256);
        spmm32_kernel<<<blocks, 256>>>(rows, cols, vals, out, nE);
    }
}